// round 1
// baseline (speedup 1.0000x reference)
#include <cuda_runtime.h>

// newIF spiking neuron forward:
//   x: [T*B, C, H, W] fp32 (T=8), thresh: [1] fp32
//   per neuron n over t: mem += x[t,n]; s=(mem>=thre); mem -= s*thre
//   new_thre = (compen>0 && cnt>0) ? min(mem-0.5*thre+cnt*thre, T*thre)/cnt : 0
//   out[t,n] = s[t] * new_thre
//
// Memory-bound: 256MB in + 256MB out. One thread handles 4 neurons (float4),
// 8 independent vector loads for MLP, spike history kept as bitmasks.

#define T_STEPS 8

__global__ __launch_bounds__(256) void newif_kernel(
    const float4* __restrict__ x,
    const float*  __restrict__ thresh,
    float4*       __restrict__ out,
    int n4)  // neurons per timestep / 4
{
    int i = blockIdx.x * blockDim.x + threadIdx.x;
    if (i >= n4) return;

    const float thre  = __ldg(thresh);
    const float half  = 0.5f * thre;
    const float tcap  = (float)T_STEPS * thre;

    // Front-batched loads: 8 independent LDG.128 (MLP=8)
    float4 xv[T_STEPS];
    #pragma unroll
    for (int t = 0; t < T_STEPS; t++)
        xv[t] = x[t * n4 + i];

    float mem[4] = {half, half, half, half};
    float cnt[4] = {0.f, 0.f, 0.f, 0.f};
    unsigned smask[4] = {0u, 0u, 0u, 0u};

    #pragma unroll
    for (int t = 0; t < T_STEPS; t++) {
        const float* xt = reinterpret_cast<const float*>(&xv[t]);
        #pragma unroll
        for (int l = 0; l < 4; l++) {
            float m = mem[l] + xt[l];
            bool s = (m >= thre);
            if (s) { m -= thre; cnt[l] += 1.f; smask[l] |= (1u << t); }
            mem[l] = m;
        }
    }

    float nt[4];
    #pragma unroll
    for (int l = 0; l < 4; l++) {
        float compen = mem[l] - half + cnt[l] * thre;
        float cv = fminf(compen, tcap);
        bool cond = (cv > 0.f) && (cnt[l] > 0.f);
        nt[l] = cond ? (cv / cnt[l]) : 0.f;
    }

    #pragma unroll
    for (int t = 0; t < T_STEPS; t++) {
        float4 o;
        o.x = (smask[0] >> t & 1u) ? nt[0] : 0.f;
        o.y = (smask[1] >> t & 1u) ? nt[1] : 0.f;
        o.z = (smask[2] >> t & 1u) ? nt[2] : 0.f;
        o.w = (smask[3] >> t & 1u) ? nt[3] : 0.f;
        out[t * n4 + i] = o;
    }
}

extern "C" void kernel_launch(void* const* d_in, const int* in_sizes, int n_in,
                              void* d_out, int out_size) {
    const float* x      = (const float*)d_in[0];
    const float* thresh = (const float*)d_in[1];
    float* out          = (float*)d_out;

    int total = in_sizes[0];          // T * B * C * H * W
    int n_per_t = total / T_STEPS;    // B * C * H * W
    int n4 = n_per_t / 4;             // float4 units per timestep

    int threads = 256;
    int blocks = (n4 + threads - 1) / threads;
    newif_kernel<<<blocks, threads>>>(
        (const float4*)x, thresh, (float4*)out, n4);
}

// round 2
// speedup vs baseline: 1.0043x; 1.0043x over previous
#include <cuda_runtime.h>

// newIF spiking neuron forward (T=8), memory-bound streaming kernel.
// R2: streaming cache hints (__ldcs / __stcs) — both streams are touch-once,
// so bypass L2 retention. 512-thread blocks for slightly deeper load pipelining.

#define T_STEPS 8

__global__ __launch_bounds__(512) void newif_kernel(
    const float4* __restrict__ x,
    const float*  __restrict__ thresh,
    float4*       __restrict__ out,
    int n4)  // neurons per timestep / 4
{
    int i = blockIdx.x * blockDim.x + threadIdx.x;
    if (i >= n4) return;

    const float thre  = __ldg(thresh);
    const float half  = 0.5f * thre;
    const float tcap  = (float)T_STEPS * thre;

    // Front-batched loads: 8 independent LDG.E.128.STRM (evict-first)
    float4 xv[T_STEPS];
    #pragma unroll
    for (int t = 0; t < T_STEPS; t++)
        xv[t] = __ldcs(&x[t * n4 + i]);

    float mem[4] = {half, half, half, half};
    float cnt[4] = {0.f, 0.f, 0.f, 0.f};
    unsigned smask[4] = {0u, 0u, 0u, 0u};

    #pragma unroll
    for (int t = 0; t < T_STEPS; t++) {
        const float* xt = reinterpret_cast<const float*>(&xv[t]);
        #pragma unroll
        for (int l = 0; l < 4; l++) {
            float m = mem[l] + xt[l];
            bool s = (m >= thre);
            if (s) { m -= thre; cnt[l] += 1.f; smask[l] |= (1u << t); }
            mem[l] = m;
        }
    }

    float nt[4];
    #pragma unroll
    for (int l = 0; l < 4; l++) {
        float compen = mem[l] - half + cnt[l] * thre;
        float cv = fminf(compen, tcap);
        bool cond = (cv > 0.f) && (cnt[l] > 0.f);
        nt[l] = cond ? (cv / cnt[l]) : 0.f;
    }

    #pragma unroll
    for (int t = 0; t < T_STEPS; t++) {
        float4 o;
        o.x = (smask[0] >> t & 1u) ? nt[0] : 0.f;
        o.y = (smask[1] >> t & 1u) ? nt[1] : 0.f;
        o.z = (smask[2] >> t & 1u) ? nt[2] : 0.f;
        o.w = (smask[3] >> t & 1u) ? nt[3] : 0.f;
        __stcs(&out[t * n4 + i], o);
    }
}

extern "C" void kernel_launch(void* const* d_in, const int* in_sizes, int n_in,
                              void* d_out, int out_size) {
    const float* x      = (const float*)d_in[0];
    const float* thresh = (const float*)d_in[1];
    float* out          = (float*)d_out;

    int total = in_sizes[0];          // T * B * C * H * W
    int n_per_t = total / T_STEPS;    // B * C * H * W
    int n4 = n_per_t / 4;             // float4 units per timestep

    int threads = 512;
    int blocks = (n4 + threads - 1) / threads;
    newif_kernel<<<blocks, threads>>>(
        (const float4*)x, thresh, (float4*)out, n4);
}